// round 12
// baseline (speedup 1.0000x reference)
#include <cuda_runtime.h>
#include <cuda_fp16.h>
#include <cstdint>
#include <math.h>

#define NN 50000
#define NEDGE 800000
#define D 256
#define NEXP 8
#define TOPK 3
#define TM 128          // GEMM M tile
#define TN 256          // GEMM N tile = full D_OUT
#define KC 32           // K halves staged per iteration
#define NSTAGE 4
#define ROWB 80         // padded smem row stride bytes (32 halves + 8 pad halves)
#define ROWW 20         // row stride in uint32 words
#define ASTAGE_W (TM * ROWW)            // words per A stage
#define BSTAGE_W (TN * ROWW)            // words per B stage
#define SM_GEMM (NSTAGE * (ASTAGE_W + BSTAGE_W) * 4)   // 122880 bytes

// ======================= scratch (static device globals) ======================
__device__ __half   g_aggh[(size_t)NN * D];         // fp16 (GEMM A)
__device__ __half   g_outh[(size_t)NN * TOPK * D];  // expert outputs per slot (fp16)
__device__ __half   g_Wh[NEXP * D * D];             // W transposed [e][n][k], fp16
__device__ int   g_deg[NN];
__device__ int   g_rowstart[NN + 1];
__device__ int   g_cursor[NN];
__device__ int   g_elist[NEDGE];
__device__ int   g_gidx[NN * TOPK];
__device__ float g_gval[NN * TOPK];
__device__ int   g_slot[NN * TOPK];
__device__ float g_imp[NEXP];
__device__ int   g_load[NEXP];
__device__ int   g_pos[NEXP];
__device__ int   g_off[NEXP + 1];
__device__ int   g_toff[NEXP + 1];
__device__ int   g_perm[NN * TOPK];
__device__ int   g_bsum[256];
__device__ int   g_is32;

__device__ __forceinline__ uint32_t h2u(__half2 h) {
    return *reinterpret_cast<uint32_t*>(&h);
}
__device__ __forceinline__ void mma16816(float* c, const uint32_t* a, const uint32_t* b) {
    asm volatile("mma.sync.aligned.m16n8k16.row.col.f32.f16.f16.f32 "
        "{%0,%1,%2,%3}, {%4,%5,%6,%7}, {%8,%9}, {%0,%1,%2,%3};"
        : "+f"(c[0]), "+f"(c[1]), "+f"(c[2]), "+f"(c[3])
        : "r"(a[0]), "r"(a[1]), "r"(a[2]), "r"(a[3]), "r"(b[0]), "r"(b[1]));
}
__device__ __forceinline__ uint32_t smem_to_u32(const void* p) {
    uint32_t a;
    asm("{ .reg .u64 t; cvta.to.shared.u64 t, %1; cvt.u32.u64 %0, t; }" : "=r"(a) : "l"(p));
    return a;
}
__device__ __forceinline__ void cpasync16(uint32_t dst, const void* src, bool valid) {
    int sz = valid ? 16 : 0;
    asm volatile("cp.async.ca.shared.global [%0], [%1], 16, %2;"
                 :: "r"(dst), "l"(src), "r"(sz));
}
#define CP_COMMIT() asm volatile("cp.async.commit_group;" ::: "memory")
#define CP_WAIT(n)  asm volatile("cp.async.wait_group %0;" :: "n"(n) : "memory")

// ---------------- init ---------------------------------------------------------
__global__ void init_kernel(const void* __restrict__ ei) {
    int i = blockIdx.x * blockDim.x + threadIdx.x;  // 196*256 = 50176
    if (i < NN) g_deg[i] = 0;
    if (i < NEXP) { g_imp[i] = 0.0f; g_load[i] = 0; g_pos[i] = 0; }
    if (i == 0) {
        const unsigned long long* q = (const unsigned long long*)ei;
        int is32 = 0;
        #pragma unroll
        for (int k = 0; k < 8; k++)
            if (q[k] >= (unsigned long long)NN) is32 = 1;
        g_is32 = is32;
    }
}

__device__ __forceinline__ void load_edge(const void* eiv, int e, int& s, int& dn) {
    if (g_is32) {
        const int* p = (const int*)eiv;
        s = p[e]; dn = p[NEDGE + e];
    } else {
        const long long* p = (const long long*)eiv;
        s = (int)p[e]; dn = (int)p[NEDGE + e];
    }
}

// ---------------- CSR build (2 edges per thread) -------------------------------
__global__ void hist_kernel(const void* __restrict__ eiv) {
    int t = blockIdx.x * blockDim.x + threadIdx.x;
    int e0 = t * 2;
    if (e0 >= NEDGE) return;
    int s, d0, d1;
    load_edge(eiv, e0, s, d0);
    atomicAdd(&g_deg[d0], 1);
    if (e0 + 1 < NEDGE) {
        load_edge(eiv, e0 + 1, s, d1);
        atomicAdd(&g_deg[d1], 1);
    }
}

__global__ void scan1_kernel() {
    __shared__ int ws[8];
    int b = blockIdx.x, t = threadIdx.x;   // grid 196, block 256
    int i = b * 256 + t;
    int v = (i < NN) ? g_deg[i] : 0;
    int x = v;
    int lane = t & 31;
    #pragma unroll
    for (int o = 1; o < 32; o <<= 1) {
        int y = __shfl_up_sync(0xffffffffu, x, o);
        if (lane >= o) x += y;
    }
    if (lane == 31) ws[t >> 5] = x;
    __syncthreads();
    if (t == 0) {
        int s = 0;
        #pragma unroll
        for (int k = 0; k < 8; k++) { int tmp = ws[k]; ws[k] = s; s += tmp; }
        g_bsum[b] = s;
    }
    __syncthreads();
    int incl = x + ws[t >> 5];
    if (i < NN) g_rowstart[i] = incl;
}

// scan3 (fused scan2): each block computes its own global offset from g_bsum
__global__ void scan3_kernel() {
    __shared__ int sb[256];
    __shared__ int s_off;
    int b = blockIdx.x, t = threadIdx.x;
    if (t < 196) sb[t] = g_bsum[t];
    __syncthreads();
    if (t == 0) {
        int s = 0;
        for (int k = 0; k < b; k++) s += sb[k];
        s_off = s;
    }
    __syncthreads();
    int i = b * 256 + t;
    if (i < NN) {
        int st = g_rowstart[i] + s_off - g_deg[i];
        g_rowstart[i] = st;
        g_cursor[i] = st;
    }
    if (i == 0) g_rowstart[NN] = NEDGE;
}

__global__ void fill_kernel(const void* __restrict__ eiv) {
    int t = blockIdx.x * blockDim.x + threadIdx.x;
    int e0 = t * 2;
    if (e0 >= NEDGE) return;
    int s0, d0, s1, d1;
    load_edge(eiv, e0, s0, d0);
    bool has1 = (e0 + 1 < NEDGE);
    if (has1) load_edge(eiv, e0 + 1, s1, d1);
    int p0 = atomicAdd(&g_cursor[d0], 1);
    g_elist[p0] = s0;
    if (has1) {
        int p1 = atomicAdd(&g_cursor[d1], 1);
        g_elist[p1] = s1;
    }
}

// ---------------- aggregate + gate fused (one warp per node) ------------------
__global__ void agg_gate_kernel(const float* __restrict__ x,
                                const float* __restrict__ Wg,
                                const float* __restrict__ bg) {
    __shared__ float simp[NEXP];
    __shared__ int   scnt[NEXP];
    int tid = threadIdx.x;
    if (tid < NEXP) { simp[tid] = 0.0f; scnt[tid] = 0; }
    __syncthreads();

    int w = blockIdx.x * 8 + (tid >> 5);   // node, exact 50000
    int lane = tid & 31;
    int start = g_rowstart[w];
    int deg = g_deg[w];
    int c0 = lane * 2, c1 = lane * 2 + 1;
    float4 a0 = make_float4(0, 0, 0, 0), a1 = make_float4(0, 0, 0, 0);
    const float4* xb = (const float4*)x;
    int i = 0, end2 = deg & ~1;
    for (; i < end2; i += 2) {
        int s0 = g_elist[start + i], s1 = g_elist[start + i + 1];
        const float4* x0 = xb + (size_t)s0 * 64;
        const float4* x1 = xb + (size_t)s1 * 64;
        float4 v0 = __ldg(x0 + c0), v1 = __ldg(x0 + c1);
        float4 w0 = __ldg(x1 + c0), w1 = __ldg(x1 + c1);
        a0.x += v0.x + w0.x; a0.y += v0.y + w0.y; a0.z += v0.z + w0.z; a0.w += v0.w + w0.w;
        a1.x += v1.x + w1.x; a1.y += v1.y + w1.y; a1.z += v1.z + w1.z; a1.w += v1.w + w1.w;
    }
    if (i < deg) {
        int s0 = g_elist[start + i];
        const float4* x0 = xb + (size_t)s0 * 64;
        float4 v0 = __ldg(x0 + c0), v1 = __ldg(x0 + c1);
        a0.x += v0.x; a0.y += v0.y; a0.z += v0.z; a0.w += v0.w;
        a1.x += v1.x; a1.y += v1.y; a1.z += v1.z; a1.w += v1.w;
    }
    uint2* ah = (uint2*)g_aggh + (size_t)w * 64;
    ah[c0] = make_uint2(h2u(__floats2half2_rn(a0.x, a0.y)), h2u(__floats2half2_rn(a0.z, a0.w)));
    ah[c1] = make_uint2(h2u(__floats2half2_rn(a1.x, a1.y)), h2u(__floats2half2_rn(a1.z, a1.w)));

    // ---- gate from registers: lane covers Wg rows lane*8 .. lane*8+7 ----
    float p[NEXP] = {0, 0, 0, 0, 0, 0, 0, 0};
    const float* av0 = &a0.x;
    const float* av1 = &a1.x;
    #pragma unroll
    for (int j = 0; j < 4; j++) {
        int row = lane * 8 + j;
        float a = av0[j];
        float4 w0 = __ldg((const float4*)(Wg + (size_t)row * NEXP));
        float4 w1 = __ldg((const float4*)(Wg + (size_t)row * NEXP) + 1);
        p[0] += a * w0.x; p[1] += a * w0.y; p[2] += a * w0.z; p[3] += a * w0.w;
        p[4] += a * w1.x; p[5] += a * w1.y; p[6] += a * w1.z; p[7] += a * w1.w;
    }
    #pragma unroll
    for (int j = 0; j < 4; j++) {
        int row = lane * 8 + 4 + j;
        float a = av1[j];
        float4 w0 = __ldg((const float4*)(Wg + (size_t)row * NEXP));
        float4 w1 = __ldg((const float4*)(Wg + (size_t)row * NEXP) + 1);
        p[0] += a * w0.x; p[1] += a * w0.y; p[2] += a * w0.z; p[3] += a * w0.w;
        p[4] += a * w1.x; p[5] += a * w1.y; p[6] += a * w1.z; p[7] += a * w1.w;
    }
    #pragma unroll
    for (int e = 0; e < NEXP; e++) {
        #pragma unroll
        for (int off = 16; off; off >>= 1)
            p[e] += __shfl_xor_sync(0xffffffffu, p[e], off);
        p[e] = fmaxf(p[e] + __ldg(bg + e), 0.0f);
    }
    if (lane == 0) {
        float v[NEXP];
        #pragma unroll
        for (int e = 0; e < NEXP; e++) v[e] = p[e];
        int idx[TOPK]; float val[TOPK];
        #pragma unroll
        for (int k = 0; k < TOPK; k++) {           // strict '>' = lowest index on ties
            int bi = 0; float bv = v[0];
            #pragma unroll
            for (int e = 1; e < NEXP; e++)
                if (v[e] > bv) { bv = v[e]; bi = e; }
            idx[k] = bi; val[k] = bv; v[bi] = -1.0f;
        }
        float mx = val[0];
        float e0 = __expf(val[0] - mx), e1 = __expf(val[1] - mx), e2 = __expf(val[2] - mx);
        float inv = 1.0f / (e0 + e1 + e2);
        float gv[TOPK] = {e0 * inv, e1 * inv, e2 * inv};
        #pragma unroll
        for (int k = 0; k < TOPK; k++) {
            g_gidx[w * TOPK + k] = idx[k];
            g_gval[w * TOPK + k] = gv[k];
            atomicAdd(&simp[idx[k]], gv[k]);
            atomicAdd(&scnt[idx[k]], 1);
        }
    }
    __syncthreads();
    if (tid < NEXP) {
        atomicAdd(&g_imp[tid], simp[tid]);
        atomicAdd(&g_load[tid], scnt[tid]);
    }
}

// ---------------- build per-expert node lists (fused offsets) -----------------
__global__ void build_lists_kernel() {
    __shared__ int lc[NEXP];
    __shared__ int lb[NEXP];
    __shared__ int loff[NEXP];
    int tid = threadIdx.x;
    if (tid < NEXP) lc[tid] = 0;
    if (tid == 0) {
        int o = 0, t = 0;
        #pragma unroll
        for (int e = 0; e < NEXP; e++) {
            loff[e] = o;
            o += g_load[e];
            t += (g_load[e] + TM - 1) / TM;
        }
        if (blockIdx.x == 0) {
            int o2 = 0, t2 = 0;
            for (int e = 0; e < NEXP; e++) {
                g_off[e] = o2; g_toff[e] = t2;
                o2 += g_load[e];
                t2 += (g_load[e] + TM - 1) / TM;
            }
            g_off[NEXP] = o2; g_toff[NEXP] = t2;
        }
    }
    __syncthreads();
    int p = blockIdx.x * blockDim.x + tid;
    bool valid = (p < NN * TOPK);
    int e = 0, rank = 0, n = 0;
    if (valid) {
        n = p / TOPK;
        e = g_gidx[p];
        rank = atomicAdd(&lc[e], 1);
    }
    __syncthreads();
    if (tid < NEXP) lb[tid] = atomicAdd(&g_pos[tid], lc[tid]);
    __syncthreads();
    if (valid) {
        int slot = loff[e] + lb[e] + rank;
        g_perm[slot] = n;
        g_slot[p] = slot;
    }
}

// ---------------- transpose W -> fp16: [e][k][n] -> [e][n][k] -----------------
__global__ void transW_kernel(const float* __restrict__ W) {
    __shared__ float tl[32][33];
    int e = blockIdx.z, kb = blockIdx.y * 32, nb = blockIdx.x * 32;
    int tx = threadIdx.x, ty = threadIdx.y;  // (32, 8)
    const float* Wb = W + (size_t)e * D * D;
    __half* Tb = g_Wh + (size_t)e * D * D;
    #pragma unroll
    for (int j = 0; j < 4; j++)
        tl[ty + 8 * j][tx] = Wb[(size_t)(kb + ty + 8 * j) * D + nb + tx];
    __syncthreads();
    #pragma unroll
    for (int j = 0; j < 4; j++)
        Tb[(size_t)(nb + ty + 8 * j) * D + kb + tx] = __float2half_rn(tl[tx][ty + 8 * j]);
}

// ---------------- fp16 m16n8k16 grouped GEMM: 128x256, 512 threads ------------
// (R10-proven mainloop: scalar LDS fragment loads, 4-stage cp.async)
__global__ void __launch_bounds__(512, 1)
moe_gemm_mma() {
    extern __shared__ uint32_t smem[];
    uint32_t* sA = smem;                         // [NSTAGE][TM*ROWW]
    uint32_t* sB = smem + NSTAGE * ASTAGE_W;     // [NSTAGE][TN*ROWW]

    int tile = blockIdx.x;
    if (tile >= g_toff[NEXP]) return;
    int e = 0;
    while (e < NEXP - 1 && tile >= g_toff[e + 1]) e++;
    int mt0 = tile - g_toff[e];
    int base = g_off[e] + mt0 * TM;
    int rows = g_load[e] - mt0 * TM;
    if (rows > TM) rows = TM;

    int tid = threadIdx.x;
    int wid = tid >> 5, lane = tid & 31;
    int gid = lane >> 2, tid4 = lane & 3;
    int wm = wid & 1, wn = wid >> 1;             // warp tile (wm*64, wn*32)

    // A staging: 4 threads per row (ra = tid>>2, qa = tid&3), 1 x 16B each
    int ra = tid >> 2, qa = tid & 3;
    const uint4* Af = nullptr;
    if (ra < rows) Af = (const uint4*)(g_aggh + (size_t)g_perm[base + ra] * D);
    // B staging: 2 threads per row (rb = tid>>1, hb = tid&1), 2 x 16B each
    int rb = tid >> 1, hb = tid & 1;
    const uint4* Bf = (const uint4*)(g_Wh + ((size_t)e * D + rb) * D);

    uint32_t sbase = smem_to_u32(smem);
    uint32_t aAddr = sbase + (uint32_t)(ra * ROWB + qa * 16);
    uint32_t bAddr = sbase + (uint32_t)(NSTAGE * ASTAGE_W * 4 + rb * ROWB + hb * 32);

    float acc[4][4][4];
    #pragma unroll
    for (int i = 0; i < 4; i++)
        #pragma unroll
        for (int j = 0; j < 4; j++)
            #pragma unroll
            for (int q = 0; q < 4; q++) acc[i][j][q] = 0.0f;

    // prologue: stage chunks 0..NSTAGE-2
    #pragma unroll
    for (int c = 0; c < NSTAGE - 1; c++) {
        uint32_t ao = aAddr + (uint32_t)(c * ASTAGE_W * 4);
        uint32_t bo = bAddr + (uint32_t)(c * BSTAGE_W * 4);
        cpasync16(ao, Af ? (const void*)(Af + c * 4 + qa) : (const void*)g_aggh, Af != nullptr);
        #pragma unroll
        for (int j = 0; j < 2; j++)
            cpasync16(bo + j * 16, (const void*)(Bf + c * 4 + hb * 2 + j), true);
        CP_COMMIT();
    }

    for (int c = 0; c < D / KC; c++) {
        if (c + NSTAGE - 1 < D / KC) {
            int cs = c + NSTAGE - 1;
            int buf = cs % NSTAGE;
            uint32_t ao = aAddr + (uint32_t)(buf * ASTAGE_W * 4);
            uint32_t bo = bAddr + (uint32_t)(buf * BSTAGE_W * 4);
            cpasync16(ao, Af ? (const void*)(Af + cs * 4 + qa) : (const void*)g_aggh, Af != nullptr);
            #pragma unroll
            for (int j = 0; j < 2; j++)
                cpasync16(bo + j * 16, (const void*)(Bf + cs * 4 + hb * 2 + j), true);
        }
        CP_COMMIT();                 // uniform group depth
        CP_WAIT(NSTAGE - 1);
        __syncthreads();

        const uint32_t* A = sA + (c % NSTAGE) * ASTAGE_W;
        const uint32_t* B = sB + (c % NSTAGE) * BSTAGE_W;
        #pragma unroll
        for (int ks = 0; ks < 2; ks++) {     // two k16 steps per 32-half chunk
            int kk = ks * 8 + tid4;          // half-pair index
            uint32_t af[4][4], bf[4][2];
            #pragma unroll
            for (int mi = 0; mi < 4; mi++) {
                int rowa = wm * 64 + mi * 16 + gid;
                af[mi][0] = A[rowa * ROWW + kk];
                af[mi][1] = A[(rowa + 8) * ROWW + kk];
                af[mi][2] = A[rowa * ROWW + kk + 4];
                af[mi][3] = A[(rowa + 8) * ROWW + kk + 4];
            }
            #pragma unroll
            for (int ni = 0; ni < 4; ni++) {
                int coln = wn * 32 + ni * 8 + gid;
                bf[ni][0] = B[coln * ROWW + kk];
                bf[ni][1] = B[coln * ROWW + kk + 4];
            }
            #pragma unroll
            for (int mi = 0; mi < 4; mi++)
                #pragma unroll
                for (int ni = 0; ni < 4; ni++)
                    mma16816(acc[mi][ni], af[mi], bf[ni]);
        }
        __syncthreads();
    }

    // epilogue: fp16 stores to g_outh (no atomics)
    #pragma unroll
    for (int mi = 0; mi < 4; mi++) {
        int mm0 = wm * 64 + mi * 16 + gid;
        int mm1 = mm0 + 8;
        __half* r0 = g_outh + (size_t)(base + mm0) * D;
        __half* r1 = g_outh + (size_t)(base + mm1) * D;
        #pragma unroll
        for (int ni = 0; ni < 4; ni++) {
            int col = wn * 32 + ni * 8 + tid4 * 2;
            if (mm0 < rows) *(uint32_t*)(r0 + col) = h2u(__floats2half2_rn(acc[mi][ni][0], acc[mi][ni][1]));
            if (mm1 < rows) *(uint32_t*)(r1 + col) = h2u(__floats2half2_rn(acc[mi][ni][2], acc[mi][ni][3]));
        }
    }
}

// ---------------- combine + loss ----------------------------------------------
__global__ void combine_kernel(const float* __restrict__ bexp, float* __restrict__ y,
                               int out_size) {
    int idx = blockIdx.x * blockDim.x + threadIdx.x;  // NN*64 exact
    int n = idx >> 6, c4 = idx & 63;
    float4 acc = make_float4(0, 0, 0, 0);
    #pragma unroll
    for (int k = 0; k < TOPK; k++) {
        int p = n * TOPK + k;
        int slot = g_slot[p];
        float gv = g_gval[p];
        int ex = g_gidx[p];
        uint2 ou = __ldg((const uint2*)(g_outh + (size_t)slot * D) + c4);
        float2 o01 = __half22float2(*reinterpret_cast<__half2*>(&ou.x));
        float2 o23 = __half22float2(*reinterpret_cast<__half2*>(&ou.y));
        float4 b = __ldg((const float4*)(bexp + (size_t)ex * D) + c4);
        acc.x += gv * (o01.x + b.x);
        acc.y += gv * (o01.y + b.y);
        acc.z += gv * (o23.x + b.z);
        acc.w += gv * (o23.y + b.w);
    }
    *((float4*)y + (size_t)n * 64 + c4) = acc;

    if (idx == 0) {
        float mi = 0.0f, ml = 0.0f;
        for (int e = 0; e < NEXP; e++) { mi += g_imp[e]; ml += (float)g_load[e]; }
        mi *= (1.0f / NEXP); ml *= (1.0f / NEXP);
        float vi = 0.0f, vl = 0.0f;
        for (int e = 0; e < NEXP; e++) {
            float di = g_imp[e] - mi;         vi += di * di;
            float dl = (float)g_load[e] - ml; vl += dl * dl;
        }
        vi *= (1.0f / (NEXP - 1));
        vl *= (1.0f / (NEXP - 1));
        float loss = 0.01f * (vi / (mi * mi + 1e-10f) + vl / (ml * ml + 1e-10f));
        if (out_size > NN * D) y[NN * D] = loss;
    }
}

// ---------------- launch ------------------------------------------------------
extern "C" void kernel_launch(void* const* d_in, const int* in_sizes, int n_in,
                              void* d_out, int out_size) {
    const float* x    = (const float*)d_in[0];
    const void*  ei   = d_in[1];
    const float* Wg   = (const float*)d_in[2];
    const float* bg   = (const float*)d_in[3];
    const float* Wexp = (const float*)d_in[4];
    const float* bexp = (const float*)d_in[5];
    float* y = (float*)d_out;

    cudaFuncSetAttribute(moe_gemm_mma, cudaFuncAttributeMaxDynamicSharedMemorySize, SM_GEMM);

    init_kernel<<<196, 256>>>(ei);
    hist_kernel<<<(NEDGE / 2 + 255) / 256, 256>>>(ei);
    scan1_kernel<<<196, 256>>>();
    scan3_kernel<<<196, 256>>>();
    fill_kernel<<<(NEDGE / 2 + 255) / 256, 256>>>(ei);
    transW_kernel<<<dim3(8, 8, NEXP), dim3(32, 8)>>>(Wexp);
    agg_gate_kernel<<<NN / 8, 256>>>(x, Wg, bg);
    build_lists_kernel<<<(NN * TOPK + 255) / 256, 256>>>();
    int max_tiles = (NN * TOPK) / TM + NEXP;  // upper bound on total tiles
    moe_gemm_mma<<<max_tiles, 512, SM_GEMM>>>();
    combine_kernel<<<NN * 64 / 256, 256>>>(bexp, y, out_size);
}

// round 13
// speedup vs baseline: 1.4942x; 1.4942x over previous
#include <cuda_runtime.h>
#include <cuda_fp16.h>
#include <cstdint>
#include <math.h>

#define NN 50000
#define NEDGE 800000
#define D 256
#define NEXP 8
#define TOPK 3
#define TM 128          // GEMM M tile
#define TN 256          // GEMM N tile = full D_OUT
#define KC 32           // K halves staged per iteration
#define NSTAGE 4
#define ROWB 80         // padded smem row stride bytes (32 halves + 8 pad halves)
#define ROWW 20         // row stride in uint32 words
#define ASTAGE_W (TM * ROWW)            // words per A stage
#define BSTAGE_W (TN * ROWW)            // words per B stage
#define SM_GEMM (NSTAGE * (ASTAGE_W + BSTAGE_W) * 4)   // 122880 bytes

// ======================= scratch (static device globals) ======================
__device__ __half   g_aggh[(size_t)NN * D];         // fp16 (GEMM A)
__device__ __half   g_outh[(size_t)NN * TOPK * D];  // expert outputs per slot (fp16)
__device__ __half   g_Wh[NEXP * D * D];             // W transposed [e][n][k], fp16
__device__ int   g_deg[NN];
__device__ int   g_rowstart[NN + 1];
__device__ int   g_cursor[NN];
__device__ int   g_elist[NEDGE];
__device__ int   g_gidx[NN * TOPK];
__device__ float g_gval[NN * TOPK];
__device__ int   g_slot[NN * TOPK];
__device__ float g_imp[NEXP];
__device__ int   g_load[NEXP];
__device__ int   g_pos[NEXP];
__device__ int   g_off[NEXP + 1];
__device__ int   g_toff[NEXP + 1];
__device__ int   g_perm[NN * TOPK];
__device__ int   g_bsum[256];
__device__ int   g_boff[256];
__device__ int   g_is32;

__device__ __forceinline__ uint32_t h2u(__half2 h) {
    return *reinterpret_cast<uint32_t*>(&h);
}
__device__ __forceinline__ void mma16816(float* c, const uint32_t* a, const uint32_t* b) {
    asm volatile("mma.sync.aligned.m16n8k16.row.col.f32.f16.f16.f32 "
        "{%0,%1,%2,%3}, {%4,%5,%6,%7}, {%8,%9}, {%0,%1,%2,%3};"
        : "+f"(c[0]), "+f"(c[1]), "+f"(c[2]), "+f"(c[3])
        : "r"(a[0]), "r"(a[1]), "r"(a[2]), "r"(a[3]), "r"(b[0]), "r"(b[1]));
}
__device__ __forceinline__ uint32_t smem_to_u32(const void* p) {
    uint32_t a;
    asm("{ .reg .u64 t; cvta.to.shared.u64 t, %1; cvt.u32.u64 %0, t; }" : "=r"(a) : "l"(p));
    return a;
}
__device__ __forceinline__ void cpasync16(uint32_t dst, const void* src, bool valid) {
    int sz = valid ? 16 : 0;
    asm volatile("cp.async.ca.shared.global [%0], [%1], 16, %2;"
                 :: "r"(dst), "l"(src), "r"(sz));
}
#define CP_COMMIT() asm volatile("cp.async.commit_group;" ::: "memory")
#define CP_WAIT(n)  asm volatile("cp.async.wait_group %0;" :: "n"(n) : "memory")

// ---------------- init ---------------------------------------------------------
__global__ void init_kernel(const void* __restrict__ ei) {
    int i = blockIdx.x * blockDim.x + threadIdx.x;  // 196*256 = 50176
    if (i < NN) g_deg[i] = 0;
    if (i < NEXP) { g_imp[i] = 0.0f; g_load[i] = 0; g_pos[i] = 0; }
    if (i == 0) {
        const unsigned long long* q = (const unsigned long long*)ei;
        int is32 = 0;
        #pragma unroll
        for (int k = 0; k < 8; k++)
            if (q[k] >= (unsigned long long)NN) is32 = 1;
        g_is32 = is32;
    }
}

__device__ __forceinline__ void load_edge(const void* eiv, int e, int& s, int& dn) {
    if (g_is32) {
        const int* p = (const int*)eiv;
        s = p[e]; dn = p[NEDGE + e];
    } else {
        const long long* p = (const long long*)eiv;
        s = (int)p[e]; dn = (int)p[NEDGE + e];
    }
}

// ---------------- CSR build ----------------------------------------------------
__global__ void hist_kernel(const void* __restrict__ eiv) {
    int e = blockIdx.x * blockDim.x + threadIdx.x;  // exactly NEDGE
    int s, dn; load_edge(eiv, e, s, dn);
    atomicAdd(&g_deg[dn], 1);
}

__global__ void scan1_kernel() {
    __shared__ int ws[8];
    int b = blockIdx.x, t = threadIdx.x;   // grid 196, block 256
    int i = b * 256 + t;
    int v = (i < NN) ? g_deg[i] : 0;
    int x = v;
    int lane = t & 31;
    #pragma unroll
    for (int o = 1; o < 32; o <<= 1) {
        int y = __shfl_up_sync(0xffffffffu, x, o);
        if (lane >= o) x += y;
    }
    if (lane == 31) ws[t >> 5] = x;
    __syncthreads();
    if (t == 0) {
        int s = 0;
        #pragma unroll
        for (int k = 0; k < 8; k++) { int tmp = ws[k]; ws[k] = s; s += tmp; }
        g_bsum[b] = s;
    }
    __syncthreads();
    int incl = x + ws[t >> 5];
    if (i < NN) g_rowstart[i] = incl;
}

__global__ void scan2_kernel() {
    __shared__ int sh[256];
    int t = threadIdx.x;
    sh[t] = (t < 196) ? g_bsum[t] : 0;
    __syncthreads();
    if (t == 0) {
        int s = 0;
        for (int k = 0; k < 196; k++) { int tmp = sh[k]; sh[k] = s; s += tmp; }
    }
    __syncthreads();
    if (t < 196) g_boff[t] = sh[t];
}

__global__ void scan3_kernel() {
    int b = blockIdx.x, t = threadIdx.x;
    int i = b * 256 + t;
    if (i < NN) {
        int st = g_rowstart[i] + g_boff[b] - g_deg[i];
        g_rowstart[i] = st;
        g_cursor[i] = st;
    }
    if (i == 0) g_rowstart[NN] = NEDGE;
}

__global__ void fill_kernel(const void* __restrict__ eiv) {
    int e = blockIdx.x * blockDim.x + threadIdx.x;
    int s, dn; load_edge(eiv, e, s, dn);
    int pos = atomicAdd(&g_cursor[dn], 1);
    g_elist[pos] = s;
}

// ---------------- aggregate + gate fused (one warp per node) ------------------
__global__ void agg_gate_kernel(const float* __restrict__ x,
                                const float* __restrict__ Wg,
                                const float* __restrict__ bg) {
    __shared__ float simp[NEXP];
    __shared__ int   scnt[NEXP];
    int tid = threadIdx.x;
    if (tid < NEXP) { simp[tid] = 0.0f; scnt[tid] = 0; }
    __syncthreads();

    int w = blockIdx.x * 8 + (tid >> 5);   // node, exact 50000
    int lane = tid & 31;
    int start = g_rowstart[w];
    int deg = g_deg[w];
    int c0 = lane * 2, c1 = lane * 2 + 1;
    float4 a0 = make_float4(0, 0, 0, 0), a1 = make_float4(0, 0, 0, 0);
    const float4* xb = (const float4*)x;
    int i = 0, end2 = deg & ~1;
    for (; i < end2; i += 2) {
        int s0 = g_elist[start + i], s1 = g_elist[start + i + 1];
        const float4* x0 = xb + (size_t)s0 * 64;
        const float4* x1 = xb + (size_t)s1 * 64;
        float4 v0 = __ldg(x0 + c0), v1 = __ldg(x0 + c1);
        float4 w0 = __ldg(x1 + c0), w1 = __ldg(x1 + c1);
        a0.x += v0.x + w0.x; a0.y += v0.y + w0.y; a0.z += v0.z + w0.z; a0.w += v0.w + w0.w;
        a1.x += v1.x + w1.x; a1.y += v1.y + w1.y; a1.z += v1.z + w1.z; a1.w += v1.w + w1.w;
    }
    if (i < deg) {
        int s0 = g_elist[start + i];
        const float4* x0 = xb + (size_t)s0 * 64;
        float4 v0 = __ldg(x0 + c0), v1 = __ldg(x0 + c1);
        a0.x += v0.x; a0.y += v0.y; a0.z += v0.z; a0.w += v0.w;
        a1.x += v1.x; a1.y += v1.y; a1.z += v1.z; a1.w += v1.w;
    }
    uint2* ah = (uint2*)g_aggh + (size_t)w * 64;
    ah[c0] = make_uint2(h2u(__floats2half2_rn(a0.x, a0.y)), h2u(__floats2half2_rn(a0.z, a0.w)));
    ah[c1] = make_uint2(h2u(__floats2half2_rn(a1.x, a1.y)), h2u(__floats2half2_rn(a1.z, a1.w)));

    // ---- gate from registers: lane covers Wg rows lane*8 .. lane*8+7 ----
    float p[NEXP] = {0, 0, 0, 0, 0, 0, 0, 0};
    const float* av0 = &a0.x;
    const float* av1 = &a1.x;
    #pragma unroll
    for (int j = 0; j < 4; j++) {
        int row = lane * 8 + j;
        float a = av0[j];
        float4 w0 = __ldg((const float4*)(Wg + (size_t)row * NEXP));
        float4 w1 = __ldg((const float4*)(Wg + (size_t)row * NEXP) + 1);
        p[0] += a * w0.x; p[1] += a * w0.y; p[2] += a * w0.z; p[3] += a * w0.w;
        p[4] += a * w1.x; p[5] += a * w1.y; p[6] += a * w1.z; p[7] += a * w1.w;
    }
    #pragma unroll
    for (int j = 0; j < 4; j++) {
        int row = lane * 8 + 4 + j;
        float a = av1[j];
        float4 w0 = __ldg((const float4*)(Wg + (size_t)row * NEXP));
        float4 w1 = __ldg((const float4*)(Wg + (size_t)row * NEXP) + 1);
        p[0] += a * w0.x; p[1] += a * w0.y; p[2] += a * w0.z; p[3] += a * w0.w;
        p[4] += a * w1.x; p[5] += a * w1.y; p[6] += a * w1.z; p[7] += a * w1.w;
    }
    #pragma unroll
    for (int e = 0; e < NEXP; e++) {
        #pragma unroll
        for (int off = 16; off; off >>= 1)
            p[e] += __shfl_xor_sync(0xffffffffu, p[e], off);
        p[e] = fmaxf(p[e] + __ldg(bg + e), 0.0f);
    }
    if (lane == 0) {
        float v[NEXP];
        #pragma unroll
        for (int e = 0; e < NEXP; e++) v[e] = p[e];
        int idx[TOPK]; float val[TOPK];
        #pragma unroll
        for (int k = 0; k < TOPK; k++) {           // strict '>' = lowest index on ties
            int bi = 0; float bv = v[0];
            #pragma unroll
            for (int e = 1; e < NEXP; e++)
                if (v[e] > bv) { bv = v[e]; bi = e; }
            idx[k] = bi; val[k] = bv; v[bi] = -1.0f;
        }
        float mx = val[0];
        float e0 = __expf(val[0] - mx), e1 = __expf(val[1] - mx), e2 = __expf(val[2] - mx);
        float inv = 1.0f / (e0 + e1 + e2);
        float gv[TOPK] = {e0 * inv, e1 * inv, e2 * inv};
        #pragma unroll
        for (int k = 0; k < TOPK; k++) {
            g_gidx[w * TOPK + k] = idx[k];
            g_gval[w * TOPK + k] = gv[k];
            atomicAdd(&simp[idx[k]], gv[k]);
            atomicAdd(&scnt[idx[k]], 1);
        }
    }
    __syncthreads();
    if (tid < NEXP) {
        atomicAdd(&g_imp[tid], simp[tid]);
        atomicAdd(&g_load[tid], scnt[tid]);
    }
}

// ---------------- per-expert offsets ------------------------------------------
__global__ void offsets_kernel() {
    if (threadIdx.x == 0 && blockIdx.x == 0) {
        int o = 0, t = 0;
        for (int e = 0; e < NEXP; e++) {
            g_off[e] = o; g_toff[e] = t;
            o += g_load[e];
            t += (g_load[e] + TM - 1) / TM;
        }
        g_off[NEXP] = o; g_toff[NEXP] = t;
    }
}

// ---------------- build per-expert node lists ---------------------------------
__global__ void build_lists_kernel() {
    __shared__ int lc[NEXP];
    __shared__ int lb[NEXP];
    int tid = threadIdx.x;
    if (tid < NEXP) lc[tid] = 0;
    __syncthreads();
    int p = blockIdx.x * blockDim.x + tid;
    bool valid = (p < NN * TOPK);
    int e = 0, rank = 0, n = 0;
    if (valid) {
        n = p / TOPK;
        e = g_gidx[p];
        rank = atomicAdd(&lc[e], 1);
    }
    __syncthreads();
    if (tid < NEXP) lb[tid] = atomicAdd(&g_pos[tid], lc[tid]);
    __syncthreads();
    if (valid) {
        int slot = g_off[e] + lb[e] + rank;
        g_perm[slot] = n;
        g_slot[p] = slot;
    }
}

// ---------------- transpose W -> fp16: [e][k][n] -> [e][n][k] -----------------
__global__ void transW_kernel(const float* __restrict__ W) {
    __shared__ float tl[32][33];
    int e = blockIdx.z, kb = blockIdx.y * 32, nb = blockIdx.x * 32;
    int tx = threadIdx.x, ty = threadIdx.y;  // (32, 8)
    const float* Wb = W + (size_t)e * D * D;
    __half* Tb = g_Wh + (size_t)e * D * D;
    #pragma unroll
    for (int j = 0; j < 4; j++)
        tl[ty + 8 * j][tx] = Wb[(size_t)(kb + ty + 8 * j) * D + nb + tx];
    __syncthreads();
    #pragma unroll
    for (int j = 0; j < 4; j++)
        Tb[(size_t)(nb + ty + 8 * j) * D + kb + tx] = __float2half_rn(tl[tx][ty + 8 * j]);
}

// ---------------- fp16 m16n8k16 grouped GEMM: 128x256, 512 threads ------------
__global__ void __launch_bounds__(512, 1)
moe_gemm_mma() {
    extern __shared__ uint32_t smem[];
    uint32_t* sA = smem;                         // [NSTAGE][TM*ROWW]
    uint32_t* sB = smem + NSTAGE * ASTAGE_W;     // [NSTAGE][TN*ROWW]

    int tile = blockIdx.x;
    if (tile >= g_toff[NEXP]) return;
    int e = 0;
    while (e < NEXP - 1 && tile >= g_toff[e + 1]) e++;
    int mt0 = tile - g_toff[e];
    int base = g_off[e] + mt0 * TM;
    int rows = g_load[e] - mt0 * TM;
    if (rows > TM) rows = TM;

    int tid = threadIdx.x;
    int wid = tid >> 5, lane = tid & 31;
    int gid = lane >> 2, tid4 = lane & 3;
    int wm = wid & 1, wn = wid >> 1;             // warp tile (wm*64, wn*32)

    // A staging: 4 threads per row (ra = tid>>2, qa = tid&3), 1 x 16B each
    int ra = tid >> 2, qa = tid & 3;
    const uint4* Af = nullptr;
    if (ra < rows) Af = (const uint4*)(g_aggh + (size_t)g_perm[base + ra] * D);
    // B staging: 2 threads per row (rb = tid>>1, hb = tid&1), 2 x 16B each
    int rb = tid >> 1, hb = tid & 1;
    const uint4* Bf = (const uint4*)(g_Wh + ((size_t)e * D + rb) * D);

    uint32_t sbase = smem_to_u32(smem);
    uint32_t aAddr = sbase + (uint32_t)(ra * ROWB + qa * 16);
    uint32_t bAddr = sbase + (uint32_t)(NSTAGE * ASTAGE_W * 4 + rb * ROWB + hb * 32);

    float acc[4][4][4];
    #pragma unroll
    for (int i = 0; i < 4; i++)
        #pragma unroll
        for (int j = 0; j < 4; j++)
            #pragma unroll
            for (int q = 0; q < 4; q++) acc[i][j][q] = 0.0f;

    // prologue: stage chunks 0..NSTAGE-2
    #pragma unroll
    for (int c = 0; c < NSTAGE - 1; c++) {
        uint32_t ao = aAddr + (uint32_t)(c * ASTAGE_W * 4);
        uint32_t bo = bAddr + (uint32_t)(c * BSTAGE_W * 4);
        cpasync16(ao, Af ? (const void*)(Af + c * 4 + qa) : (const void*)g_aggh, Af != nullptr);
        #pragma unroll
        for (int j = 0; j < 2; j++)
            cpasync16(bo + j * 16, (const void*)(Bf + c * 4 + hb * 2 + j), true);
        CP_COMMIT();
    }

    for (int c = 0; c < D / KC; c++) {
        if (c + NSTAGE - 1 < D / KC) {
            int cs = c + NSTAGE - 1;
            int buf = cs % NSTAGE;
            uint32_t ao = aAddr + (uint32_t)(buf * ASTAGE_W * 4);
            uint32_t bo = bAddr + (uint32_t)(buf * BSTAGE_W * 4);
            cpasync16(ao, Af ? (const void*)(Af + cs * 4 + qa) : (const void*)g_aggh, Af != nullptr);
            #pragma unroll
            for (int j = 0; j < 2; j++)
                cpasync16(bo + j * 16, (const void*)(Bf + cs * 4 + hb * 2 + j), true);
        }
        CP_COMMIT();                 // uniform group depth
        CP_WAIT(NSTAGE - 1);
        __syncthreads();

        const uint32_t* A = sA + (c % NSTAGE) * ASTAGE_W;
        const uint32_t* B = sB + (c % NSTAGE) * BSTAGE_W;
        #pragma unroll
        for (int ks = 0; ks < 2; ks++) {     // two k16 steps per 32-half chunk
            int kk = ks * 8 + tid4;          // half-pair index
            uint32_t af[4][4], bf[4][2];
            #pragma unroll
            for (int mi = 0; mi < 4; mi++) {
                int rowa = wm * 64 + mi * 16 + gid;
                af[mi][0] = A[rowa * ROWW + kk];
                af[mi][1] = A[(rowa + 8) * ROWW + kk];
                af[mi][2] = A[rowa * ROWW + kk + 4];
                af[mi][3] = A[(rowa + 8) * ROWW + kk + 4];
            }
            #pragma unroll
            for (int ni = 0; ni < 4; ni++) {
                int coln = wn * 32 + ni * 8 + gid;
                bf[ni][0] = B[coln * ROWW + kk];
                bf[ni][1] = B[coln * ROWW + kk + 4];
            }
            #pragma unroll
            for (int mi = 0; mi < 4; mi++)
                #pragma unroll
                for (int ni = 0; ni < 4; ni++)
                    mma16816(acc[mi][ni], af[mi], bf[ni]);
        }
        __syncthreads();
    }

    // epilogue: fp16 stores to g_outh (no atomics)
    #pragma unroll
    for (int mi = 0; mi < 4; mi++) {
        int mm0 = wm * 64 + mi * 16 + gid;
        int mm1 = mm0 + 8;
        __half* r0 = g_outh + (size_t)(base + mm0) * D;
        __half* r1 = g_outh + (size_t)(base + mm1) * D;
        #pragma unroll
        for (int ni = 0; ni < 4; ni++) {
            int col = wn * 32 + ni * 8 + tid4 * 2;
            if (mm0 < rows) *(uint32_t*)(r0 + col) = h2u(__floats2half2_rn(acc[mi][ni][0], acc[mi][ni][1]));
            if (mm1 < rows) *(uint32_t*)(r1 + col) = h2u(__floats2half2_rn(acc[mi][ni][2], acc[mi][ni][3]));
        }
    }
}

// ---------------- combine + loss ----------------------------------------------
__global__ void combine_kernel(const float* __restrict__ bexp, float* __restrict__ y,
                               int out_size) {
    int idx = blockIdx.x * blockDim.x + threadIdx.x;  // NN*64 exact
    int n = idx >> 6, c4 = idx & 63;
    float4 acc = make_float4(0, 0, 0, 0);
    #pragma unroll
    for (int k = 0; k < TOPK; k++) {
        int p = n * TOPK + k;
        int slot = g_slot[p];
        float gv = g_gval[p];
        int ex = g_gidx[p];
        uint2 ou = __ldg((const uint2*)(g_outh + (size_t)slot * D) + c4);
        float2 o01 = __half22float2(*reinterpret_cast<__half2*>(&ou.x));
        float2 o23 = __half22float2(*reinterpret_cast<__half2*>(&ou.y));
        float4 b = __ldg((const float4*)(bexp + (size_t)ex * D) + c4);
        acc.x += gv * (o01.x + b.x);
        acc.y += gv * (o01.y + b.y);
        acc.z += gv * (o23.x + b.z);
        acc.w += gv * (o23.y + b.w);
    }
    *((float4*)y + (size_t)n * 64 + c4) = acc;

    if (idx == 0) {
        float mi = 0.0f, ml = 0.0f;
        for (int e = 0; e < NEXP; e++) { mi += g_imp[e]; ml += (float)g_load[e]; }
        mi *= (1.0f / NEXP); ml *= (1.0f / NEXP);
        float vi = 0.0f, vl = 0.0f;
        for (int e = 0; e < NEXP; e++) {
            float di = g_imp[e] - mi;         vi += di * di;
            float dl = (float)g_load[e] - ml; vl += dl * dl;
        }
        vi *= (1.0f / (NEXP - 1));
        vl *= (1.0f / (NEXP - 1));
        float loss = 0.01f * (vi / (mi * mi + 1e-10f) + vl / (ml * ml + 1e-10f));
        if (out_size > NN * D) y[NN * D] = loss;
    }
}

// ---------------- launch ------------------------------------------------------
extern "C" void kernel_launch(void* const* d_in, const int* in_sizes, int n_in,
                              void* d_out, int out_size) {
    const float* x    = (const float*)d_in[0];
    const void*  ei   = d_in[1];
    const float* Wg   = (const float*)d_in[2];
    const float* bg   = (const float*)d_in[3];
    const float* Wexp = (const float*)d_in[4];
    const float* bexp = (const float*)d_in[5];
    float* y = (float*)d_out;

    cudaFuncSetAttribute(moe_gemm_mma, cudaFuncAttributeMaxDynamicSharedMemorySize, SM_GEMM);

    init_kernel<<<196, 256>>>(ei);
    hist_kernel<<<NEDGE / 256, 256>>>(ei);
    scan1_kernel<<<196, 256>>>();
    scan2_kernel<<<1, 256>>>();
    scan3_kernel<<<196, 256>>>();
    fill_kernel<<<NEDGE / 256, 256>>>(ei);
    transW_kernel<<<dim3(8, 8, NEXP), dim3(32, 8)>>>(Wexp);
    agg_gate_kernel<<<NN / 8, 256>>>(x, Wg, bg);
    offsets_kernel<<<1, 32>>>();
    build_lists_kernel<<<(NN * TOPK + 255) / 256, 256>>>();
    int max_tiles = (NN * TOPK) / TM + NEXP;  // upper bound on total tiles
    moe_gemm_mma<<<max_tiles, 512, SM_GEMM>>>();
    combine_kernel<<<NN * 64 / 256, 256>>>(bexp, y, out_size);
}

// round 15
// speedup vs baseline: 1.5033x; 1.0061x over previous
#include <cuda_runtime.h>
#include <cuda_fp16.h>
#include <cstdint>
#include <math.h>

#define NN 50000
#define NEDGE 800000
#define D 256
#define NEXP 8
#define TOPK 3
#define TM 128          // GEMM M tile
#define TN 256          // GEMM N tile = full D_OUT
#define KC 32           // K halves staged per iteration
#define NSTAGE 4
#define ROWB 80         // padded smem row stride bytes (32 halves + 8 pad halves)
#define ROWW 20         // row stride in uint32 words
#define ASTAGE_W (TM * ROWW)            // words per A stage
#define BSTAGE_W (TN * ROWW)            // words per B stage
#define SM_GEMM (NSTAGE * (ASTAGE_W + BSTAGE_W) * 4)   // 122880 bytes

// ======================= scratch (static device globals) ======================
__device__ __half   g_xh[(size_t)NN * D];           // fp16 mirror of x
__device__ float    g_xg[NN * NEXP];                // x @ W_gate (fp32, exact)
__device__ __half   g_aggh[(size_t)NN * D];         // fp16 (GEMM A)
__device__ __half   g_outh[(size_t)NN * TOPK * D];  // expert outputs per slot (fp16)
__device__ __half   g_Wh[NEXP * D * D];             // W transposed [e][n][k], fp16
__device__ int   g_deg[NN];
__device__ int   g_rowstart[NN + 1];
__device__ int   g_cursor[NN];
__device__ int   g_elist[NEDGE];
__device__ int   g_gidx[NN * TOPK];
__device__ float g_gval[NN * TOPK];
__device__ int   g_slot[NN * TOPK];
__device__ float g_imp[NEXP];
__device__ int   g_load[NEXP];
__device__ int   g_pos[NEXP];
__device__ int   g_off[NEXP + 1];
__device__ int   g_toff[NEXP + 1];
__device__ int   g_perm[NN * TOPK];
__device__ int   g_bsum[256];
__device__ int   g_boff[256];
__device__ int   g_is32;

__device__ __forceinline__ uint32_t h2u(__half2 h) {
    return *reinterpret_cast<uint32_t*>(&h);
}
__device__ __forceinline__ void mma16816(float* c, const uint32_t* a, const uint32_t* b) {
    asm volatile("mma.sync.aligned.m16n8k16.row.col.f32.f16.f16.f32 "
        "{%0,%1,%2,%3}, {%4,%5,%6,%7}, {%8,%9}, {%0,%1,%2,%3};"
        : "+f"(c[0]), "+f"(c[1]), "+f"(c[2]), "+f"(c[3])
        : "r"(a[0]), "r"(a[1]), "r"(a[2]), "r"(a[3]), "r"(b[0]), "r"(b[1]));
}
__device__ __forceinline__ uint32_t smem_to_u32(const void* p) {
    uint32_t a;
    asm("{ .reg .u64 t; cvta.to.shared.u64 t, %1; cvt.u32.u64 %0, t; }" : "=r"(a) : "l"(p));
    return a;
}
__device__ __forceinline__ void cpasync16(uint32_t dst, const void* src, bool valid) {
    int sz = valid ? 16 : 0;
    asm volatile("cp.async.ca.shared.global [%0], [%1], 16, %2;"
                 :: "r"(dst), "l"(src), "r"(sz));
}
#define CP_COMMIT() asm volatile("cp.async.commit_group;" ::: "memory")
#define CP_WAIT(n)  asm volatile("cp.async.wait_group %0;" :: "n"(n) : "memory")

// ---------------- init ---------------------------------------------------------
__global__ void init_kernel(const void* __restrict__ ei) {
    int i = blockIdx.x * blockDim.x + threadIdx.x;  // 196*256 = 50176
    if (i < NN) g_deg[i] = 0;
    if (i < NEXP) { g_imp[i] = 0.0f; g_load[i] = 0; g_pos[i] = 0; }
    if (i == 0) {
        const unsigned long long* q = (const unsigned long long*)ei;
        int is32 = 0;
        #pragma unroll
        for (int k = 0; k < 8; k++)
            if (q[k] >= (unsigned long long)NN) is32 = 1;
        g_is32 = is32;
    }
}

__device__ __forceinline__ void load_edge(const void* eiv, int e, int& s, int& dn) {
    if (g_is32) {
        const int* p = (const int*)eiv;
        s = p[e]; dn = p[NEDGE + e];
    } else {
        const long long* p = (const long long*)eiv;
        s = (int)p[e]; dn = (int)p[NEDGE + e];
    }
}

// ---------------- CSR build ----------------------------------------------------
__global__ void hist_kernel(const void* __restrict__ eiv) {
    int e = blockIdx.x * blockDim.x + threadIdx.x;  // exactly NEDGE
    int s, dn; load_edge(eiv, e, s, dn);
    atomicAdd(&g_deg[dn], 1);
}

__global__ void scan1_kernel() {
    __shared__ int ws[8];
    int b = blockIdx.x, t = threadIdx.x;   // grid 196, block 256
    int i = b * 256 + t;
    int v = (i < NN) ? g_deg[i] : 0;
    int x = v;
    int lane = t & 31;
    #pragma unroll
    for (int o = 1; o < 32; o <<= 1) {
        int y = __shfl_up_sync(0xffffffffu, x, o);
        if (lane >= o) x += y;
    }
    if (lane == 31) ws[t >> 5] = x;
    __syncthreads();
    if (t == 0) {
        int s = 0;
        #pragma unroll
        for (int k = 0; k < 8; k++) { int tmp = ws[k]; ws[k] = s; s += tmp; }
        g_bsum[b] = s;
    }
    __syncthreads();
    int incl = x + ws[t >> 5];
    if (i < NN) g_rowstart[i] = incl;
}

__global__ void scan2_kernel() {
    __shared__ int sh[256];
    int t = threadIdx.x;
    sh[t] = (t < 196) ? g_bsum[t] : 0;
    __syncthreads();
    if (t == 0) {
        int s = 0;
        for (int k = 0; k < 196; k++) { int tmp = sh[k]; sh[k] = s; s += tmp; }
    }
    __syncthreads();
    if (t < 196) g_boff[t] = sh[t];
}

__global__ void scan3_kernel() {
    int b = blockIdx.x, t = threadIdx.x;
    int i = b * 256 + t;
    if (i < NN) {
        int st = g_rowstart[i] + g_boff[b] - g_deg[i];
        g_rowstart[i] = st;
        g_cursor[i] = st;
    }
    if (i == 0) g_rowstart[NN] = NEDGE;
}

__global__ void fill_kernel(const void* __restrict__ eiv) {
    int e = blockIdx.x * blockDim.x + threadIdx.x;
    int s, dn; load_edge(eiv, e, s, dn);
    int pos = atomicAdd(&g_cursor[dn], 1);
    g_elist[pos] = s;
}

// ---------------- prep: x -> fp16 mirror + xg = x @ Wg (one warp per row) -----
__global__ void prep_kernel(const float* __restrict__ x, const float* __restrict__ Wg) {
    int w = blockIdx.x * 8 + (threadIdx.x >> 5);   // row, exact 50000
    int lane = threadIdx.x & 31;
    int c0 = lane * 2, c1 = lane * 2 + 1;
    const float4* xr = (const float4*)x + (size_t)w * 64;
    float4 a0 = __ldg(xr + c0), a1 = __ldg(xr + c1);

    // fp16 mirror
    uint2* xh = (uint2*)g_xh + (size_t)w * 64;
    xh[c0] = make_uint2(h2u(__floats2half2_rn(a0.x, a0.y)), h2u(__floats2half2_rn(a0.z, a0.w)));
    xh[c1] = make_uint2(h2u(__floats2half2_rn(a1.x, a1.y)), h2u(__floats2half2_rn(a1.z, a1.w)));

    // xg partial: lane covers Wg rows lane*8 .. lane*8+7
    float p[NEXP] = {0, 0, 0, 0, 0, 0, 0, 0};
    const float* av0 = &a0.x;
    const float* av1 = &a1.x;
    #pragma unroll
    for (int j = 0; j < 4; j++) {
        int row = lane * 8 + j;
        float a = av0[j];
        float4 w0 = __ldg((const float4*)(Wg + (size_t)row * NEXP));
        float4 w1 = __ldg((const float4*)(Wg + (size_t)row * NEXP) + 1);
        p[0] += a * w0.x; p[1] += a * w0.y; p[2] += a * w0.z; p[3] += a * w0.w;
        p[4] += a * w1.x; p[5] += a * w1.y; p[6] += a * w1.z; p[7] += a * w1.w;
    }
    #pragma unroll
    for (int j = 0; j < 4; j++) {
        int row = lane * 8 + 4 + j;
        float a = av1[j];
        float4 w0 = __ldg((const float4*)(Wg + (size_t)row * NEXP));
        float4 w1 = __ldg((const float4*)(Wg + (size_t)row * NEXP) + 1);
        p[0] += a * w0.x; p[1] += a * w0.y; p[2] += a * w0.z; p[3] += a * w0.w;
        p[4] += a * w1.x; p[5] += a * w1.y; p[6] += a * w1.z; p[7] += a * w1.w;
    }
    #pragma unroll
    for (int e = 0; e < NEXP; e++) {
        #pragma unroll
        for (int off = 16; off; off >>= 1)
            p[e] += __shfl_xor_sync(0xffffffffu, p[e], off);
    }
    if (lane == 0) {
        float* xgr = g_xg + w * NEXP;
        #pragma unroll
        for (int e = 0; e < NEXP; e++) xgr[e] = p[e];
    }
}

// ---------------- aggregate (fp16 gather) + gate (exact fp32 via xg) ----------
__global__ void agg_gate_kernel(const float* __restrict__ bg) {
    __shared__ float simp[NEXP];
    __shared__ int   scnt[NEXP];
    int tid = threadIdx.x;
    if (tid < NEXP) { simp[tid] = 0.0f; scnt[tid] = 0; }
    __syncthreads();

    int w = blockIdx.x * 8 + (tid >> 5);   // node, exact 50000
    int lane = tid & 31;
    int start = g_rowstart[w];
    int deg = g_deg[w];
    float a[8] = {0, 0, 0, 0, 0, 0, 0, 0};  // cols lane*8 .. lane*8+7 (fp32 accum)
    float lg = 0.0f;                          // lanes 0-7: logit (lane)
    const uint4* xhb = (const uint4*)g_xh;    // row = 32 uint4
    bool glane = (lane < NEXP);

    int i = 0, end2 = deg & ~1;
    for (; i < end2; i += 2) {
        int s0 = g_elist[start + i], s1 = g_elist[start + i + 1];
        uint4 u0 = __ldg(xhb + (size_t)s0 * 32 + lane);
        uint4 u1 = __ldg(xhb + (size_t)s1 * 32 + lane);
        float g0 = 0.0f, g1 = 0.0f;
        if (glane) {
            g0 = __ldg(g_xg + s0 * NEXP + lane);
            g1 = __ldg(g_xg + s1 * NEXP + lane);
        }
        float2 f0 = __half22float2(*reinterpret_cast<__half2*>(&u0.x));
        float2 f1 = __half22float2(*reinterpret_cast<__half2*>(&u0.y));
        float2 f2 = __half22float2(*reinterpret_cast<__half2*>(&u0.z));
        float2 f3 = __half22float2(*reinterpret_cast<__half2*>(&u0.w));
        a[0] += f0.x; a[1] += f0.y; a[2] += f1.x; a[3] += f1.y;
        a[4] += f2.x; a[5] += f2.y; a[6] += f3.x; a[7] += f3.y;
        f0 = __half22float2(*reinterpret_cast<__half2*>(&u1.x));
        f1 = __half22float2(*reinterpret_cast<__half2*>(&u1.y));
        f2 = __half22float2(*reinterpret_cast<__half2*>(&u1.z));
        f3 = __half22float2(*reinterpret_cast<__half2*>(&u1.w));
        a[0] += f0.x; a[1] += f0.y; a[2] += f1.x; a[3] += f1.y;
        a[4] += f2.x; a[5] += f2.y; a[6] += f3.x; a[7] += f3.y;
        lg += g0 + g1;
    }
    if (i < deg) {
        int s0 = g_elist[start + i];
        uint4 u0 = __ldg(xhb + (size_t)s0 * 32 + lane);
        if (glane) lg += __ldg(g_xg + s0 * NEXP + lane);
        float2 f0 = __half22float2(*reinterpret_cast<__half2*>(&u0.x));
        float2 f1 = __half22float2(*reinterpret_cast<__half2*>(&u0.y));
        float2 f2 = __half22float2(*reinterpret_cast<__half2*>(&u0.z));
        float2 f3 = __half22float2(*reinterpret_cast<__half2*>(&u0.w));
        a[0] += f0.x; a[1] += f0.y; a[2] += f1.x; a[3] += f1.y;
        a[4] += f2.x; a[5] += f2.y; a[6] += f3.x; a[7] += f3.y;
    }

    // write fp16 A row (cols lane*8 .. lane*8+7)
    uint2* ah = (uint2*)g_aggh + (size_t)w * 64;
    ah[lane * 2]     = make_uint2(h2u(__floats2half2_rn(a[0], a[1])), h2u(__floats2half2_rn(a[2], a[3])));
    ah[lane * 2 + 1] = make_uint2(h2u(__floats2half2_rn(a[4], a[5])), h2u(__floats2half2_rn(a[6], a[7])));

    // gate: relu(logit + bias) on lanes 0-7 (exact fp32 path)
    lg = fmaxf(lg + __ldg(bg + (lane & (NEXP - 1))), 0.0f);
    // CONVERGED broadcast: every lane gathers all 8 logits (no shfl in divergence)
    float v[NEXP];
    #pragma unroll
    for (int e = 0; e < NEXP; e++)
        v[e] = __shfl_sync(0xffffffffu, lg, e);
    if (lane == 0) {
        int idx[TOPK]; float val[TOPK];
        #pragma unroll
        for (int k = 0; k < TOPK; k++) {           // strict '>' = lowest index on ties
            int bi = 0; float bv = v[0];
            #pragma unroll
            for (int e = 1; e < NEXP; e++)
                if (v[e] > bv) { bv = v[e]; bi = e; }
            idx[k] = bi; val[k] = bv; v[bi] = -1.0f;
        }
        float mx = val[0];
        float e0 = __expf(val[0] - mx), e1 = __expf(val[1] - mx), e2 = __expf(val[2] - mx);
        float inv = 1.0f / (e0 + e1 + e2);
        float gv[TOPK] = {e0 * inv, e1 * inv, e2 * inv};
        #pragma unroll
        for (int k = 0; k < TOPK; k++) {
            g_gidx[w * TOPK + k] = idx[k];
            g_gval[w * TOPK + k] = gv[k];
            atomicAdd(&simp[idx[k]], gv[k]);
            atomicAdd(&scnt[idx[k]], 1);
        }
    }
    __syncthreads();
    if (tid < NEXP) {
        atomicAdd(&g_imp[tid], simp[tid]);
        atomicAdd(&g_load[tid], scnt[tid]);
    }
}

// ---------------- per-expert offsets ------------------------------------------
__global__ void offsets_kernel() {
    if (threadIdx.x == 0 && blockIdx.x == 0) {
        int o = 0, t = 0;
        for (int e = 0; e < NEXP; e++) {
            g_off[e] = o; g_toff[e] = t;
            o += g_load[e];
            t += (g_load[e] + TM - 1) / TM;
        }
        g_off[NEXP] = o; g_toff[NEXP] = t;
    }
}

// ---------------- build per-expert node lists ---------------------------------
__global__ void build_lists_kernel() {
    __shared__ int lc[NEXP];
    __shared__ int lb[NEXP];
    int tid = threadIdx.x;
    if (tid < NEXP) lc[tid] = 0;
    __syncthreads();
    int p = blockIdx.x * blockDim.x + tid;
    bool valid = (p < NN * TOPK);
    int e = 0, rank = 0, n = 0;
    if (valid) {
        n = p / TOPK;
        e = g_gidx[p];
        rank = atomicAdd(&lc[e], 1);
    }
    __syncthreads();
    if (tid < NEXP) lb[tid] = atomicAdd(&g_pos[tid], lc[tid]);
    __syncthreads();
    if (valid) {
        int slot = g_off[e] + lb[e] + rank;
        g_perm[slot] = n;
        g_slot[p] = slot;
    }
}

// ---------------- transpose W -> fp16: [e][k][n] -> [e][n][k] -----------------
__global__ void transW_kernel(const float* __restrict__ W) {
    __shared__ float tl[32][33];
    int e = blockIdx.z, kb = blockIdx.y * 32, nb = blockIdx.x * 32;
    int tx = threadIdx.x, ty = threadIdx.y;  // (32, 8)
    const float* Wb = W + (size_t)e * D * D;
    __half* Tb = g_Wh + (size_t)e * D * D;
    #pragma unroll
    for (int j = 0; j < 4; j++)
        tl[ty + 8 * j][tx] = Wb[(size_t)(kb + ty + 8 * j) * D + nb + tx];
    __syncthreads();
    #pragma unroll
    for (int j = 0; j < 4; j++)
        Tb[(size_t)(nb + ty + 8 * j) * D + kb + tx] = __float2half_rn(tl[tx][ty + 8 * j]);
}

// ---------------- fp16 m16n8k16 grouped GEMM: 128x256, 512 threads ------------
__global__ void __launch_bounds__(512, 1)
moe_gemm_mma() {
    extern __shared__ uint32_t smem[];
    uint32_t* sA = smem;                         // [NSTAGE][TM*ROWW]
    uint32_t* sB = smem + NSTAGE * ASTAGE_W;     // [NSTAGE][TN*ROWW]

    int tile = blockIdx.x;
    if (tile >= g_toff[NEXP]) return;
    int e = 0;
    while (e < NEXP - 1 && tile >= g_toff[e + 1]) e++;
    int mt0 = tile - g_toff[e];
    int base = g_off[e] + mt0 * TM;
    int rows = g_load[e] - mt0 * TM;
    if (rows > TM) rows = TM;

    int tid = threadIdx.x;
    int wid = tid >> 5, lane = tid & 31;
    int gid = lane >> 2, tid4 = lane & 3;
    int wm = wid & 1, wn = wid >> 1;             // warp tile (wm*64, wn*32)

    // A staging: 4 threads per row (ra = tid>>2, qa = tid&3), 1 x 16B each
    int ra = tid >> 2, qa = tid & 3;
    const uint4* Af = nullptr;
    if (ra < rows) Af = (const uint4*)(g_aggh + (size_t)g_perm[base + ra] * D);
    // B staging: 2 threads per row (rb = tid>>1, hb = tid&1), 2 x 16B each
    int rb = tid >> 1, hb = tid & 1;
    const uint4* Bf = (const uint4*)(g_Wh + ((size_t)e * D + rb) * D);

    uint32_t sbase = smem_to_u32(smem);
    uint32_t aAddr = sbase + (uint32_t)(ra * ROWB + qa * 16);
    uint32_t bAddr = sbase + (uint32_t)(NSTAGE * ASTAGE_W * 4 + rb * ROWB + hb * 32);

    float acc[4][4][4];
    #pragma unroll
    for (int i = 0; i < 4; i++)
        #pragma unroll
        for (int j = 0; j < 4; j++)
            #pragma unroll
            for (int q = 0; q < 4; q++) acc[i][j][q] = 0.0f;

    // prologue: stage chunks 0..NSTAGE-2
    #pragma unroll
    for (int c = 0; c < NSTAGE - 1; c++) {
        uint32_t ao = aAddr + (uint32_t)(c * ASTAGE_W * 4);
        uint32_t bo = bAddr + (uint32_t)(c * BSTAGE_W * 4);
        cpasync16(ao, Af ? (const void*)(Af + c * 4 + qa) : (const void*)g_aggh, Af != nullptr);
        #pragma unroll
        for (int j = 0; j < 2; j++)
            cpasync16(bo + j * 16, (const void*)(Bf + c * 4 + hb * 2 + j), true);
        CP_COMMIT();
    }

    for (int c = 0; c < D / KC; c++) {
        if (c + NSTAGE - 1 < D / KC) {
            int cs = c + NSTAGE - 1;
            int buf = cs % NSTAGE;
            uint32_t ao = aAddr + (uint32_t)(buf * ASTAGE_W * 4);
            uint32_t bo = bAddr + (uint32_t)(buf * BSTAGE_W * 4);
            cpasync16(ao, Af ? (const void*)(Af + cs * 4 + qa) : (const void*)g_aggh, Af != nullptr);
            #pragma unroll
            for (int j = 0; j < 2; j++)
                cpasync16(bo + j * 16, (const void*)(Bf + cs * 4 + hb * 2 + j), true);
        }
        CP_COMMIT();                 // uniform group depth
        CP_WAIT(NSTAGE - 1);
        __syncthreads();

        const uint32_t* A = sA + (c % NSTAGE) * ASTAGE_W;
        const uint32_t* B = sB + (c % NSTAGE) * BSTAGE_W;
        #pragma unroll
        for (int ks = 0; ks < 2; ks++) {     // two k16 steps per 32-half chunk
            int kk = ks * 8 + tid4;          // half-pair index
            uint32_t af[4][4], bf[4][2];
            #pragma unroll
            for (int mi = 0; mi < 4; mi++) {
                int rowa = wm * 64 + mi * 16 + gid;
                af[mi][0] = A[rowa * ROWW + kk];
                af[mi][1] = A[(rowa + 8) * ROWW + kk];
                af[mi][2] = A[rowa * ROWW + kk + 4];
                af[mi][3] = A[(rowa + 8) * ROWW + kk + 4];
            }
            #pragma unroll
            for (int ni = 0; ni < 4; ni++) {
                int coln = wn * 32 + ni * 8 + gid;
                bf[ni][0] = B[coln * ROWW + kk];
                bf[ni][1] = B[coln * ROWW + kk + 4];
            }
            #pragma unroll
            for (int mi = 0; mi < 4; mi++)
                #pragma unroll
                for (int ni = 0; ni < 4; ni++)
                    mma16816(acc[mi][ni], af[mi], bf[ni]);
        }
        __syncthreads();
    }

    // epilogue: fp16 stores to g_outh (no atomics)
    #pragma unroll
    for (int mi = 0; mi < 4; mi++) {
        int mm0 = wm * 64 + mi * 16 + gid;
        int mm1 = mm0 + 8;
        __half* r0 = g_outh + (size_t)(base + mm0) * D;
        __half* r1 = g_outh + (size_t)(base + mm1) * D;
        #pragma unroll
        for (int ni = 0; ni < 4; ni++) {
            int col = wn * 32 + ni * 8 + tid4 * 2;
            if (mm0 < rows) *(uint32_t*)(r0 + col) = h2u(__floats2half2_rn(acc[mi][ni][0], acc[mi][ni][1]));
            if (mm1 < rows) *(uint32_t*)(r1 + col) = h2u(__floats2half2_rn(acc[mi][ni][2], acc[mi][ni][3]));
        }
    }
}

// ---------------- combine + loss ----------------------------------------------
__global__ void combine_kernel(const float* __restrict__ bexp, float* __restrict__ y,
                               int out_size) {
    int idx = blockIdx.x * blockDim.x + threadIdx.x;  // NN*64 exact
    int n = idx >> 6, c4 = idx & 63;
    float4 acc = make_float4(0, 0, 0, 0);
    #pragma unroll
    for (int k = 0; k < TOPK; k++) {
        int p = n * TOPK + k;
        int slot = g_slot[p];
        float gv = g_gval[p];
        int ex = g_gidx[p];
        uint2 ou = __ldg((const uint2*)(g_outh + (size_t)slot * D) + c4);
        float2 o01 = __half22float2(*reinterpret_cast<__half2*>(&ou.x));
        float2 o23 = __half22float2(*reinterpret_cast<__half2*>(&ou.y));
        float4 b = __ldg((const float4*)(bexp + (size_t)ex * D) + c4);
        acc.x += gv * (o01.x + b.x);
        acc.y += gv * (o01.y + b.y);
        acc.z += gv * (o23.x + b.z);
        acc.w += gv * (o23.y + b.w);
    }
    *((float4*)y + (size_t)n * 64 + c4) = acc;

    if (idx == 0) {
        float mi = 0.0f, ml = 0.0f;
        for (int e = 0; e < NEXP; e++) { mi += g_imp[e]; ml += (float)g_load[e]; }
        mi *= (1.0f / NEXP); ml *= (1.0f / NEXP);
        float vi = 0.0f, vl = 0.0f;
        for (int e = 0; e < NEXP; e++) {
            float di = g_imp[e] - mi;         vi += di * di;
            float dl = (float)g_load[e] - ml; vl += dl * dl;
        }
        vi *= (1.0f / (NEXP - 1));
        vl *= (1.0f / (NEXP - 1));
        float loss = 0.01f * (vi / (mi * mi + 1e-10f) + vl / (ml * ml + 1e-10f));
        if (out_size > NN * D) y[NN * D] = loss;
    }
}

// ---------------- launch ------------------------------------------------------
extern "C" void kernel_launch(void* const* d_in, const int* in_sizes, int n_in,
                              void* d_out, int out_size) {
    const float* x    = (const float*)d_in[0];
    const void*  ei   = d_in[1];
    const float* Wg   = (const float*)d_in[2];
    const float* bg   = (const float*)d_in[3];
    const float* Wexp = (const float*)d_in[4];
    const float* bexp = (const float*)d_in[5];
    float* y = (float*)d_out;

    cudaFuncSetAttribute(moe_gemm_mma, cudaFuncAttributeMaxDynamicSharedMemorySize, SM_GEMM);

    init_kernel<<<196, 256>>>(ei);
    hist_kernel<<<NEDGE / 256, 256>>>(ei);
    scan1_kernel<<<196, 256>>>();
    scan2_kernel<<<1, 256>>>();
    scan3_kernel<<<196, 256>>>();
    fill_kernel<<<NEDGE / 256, 256>>>(ei);
    prep_kernel<<<NN / 8, 256>>>(x, Wg);
    transW_kernel<<<dim3(8, 8, NEXP), dim3(32, 8)>>>(Wexp);
    agg_gate_kernel<<<NN / 8, 256>>>(bg);
    offsets_kernel<<<1, 32>>>();
    build_lists_kernel<<<(NN * TOPK + 255) / 256, 256>>>();
    int max_tiles = (NN * TOPK) / TM + NEXP;  // upper bound on total tiles
    moe_gemm_mma<<<max_tiles, 512, SM_GEMM>>>();
    combine_kernel<<<NN * 64 / 256, 256>>>(bexp, y, out_size);
}

// round 16
// speedup vs baseline: 1.5757x; 1.0482x over previous
#include <cuda_runtime.h>
#include <cuda_fp16.h>
#include <cstdint>
#include <math.h>

#define NN 50000
#define NEDGE 800000
#define D 256
#define NEXP 8
#define TOPK 3
#define TM 128          // GEMM M tile
#define TN 256          // GEMM N tile = full D_OUT
#define KC 64           // K halves staged per iteration (4 chunks over K=256)
#define NSTAGE 2
#define ROWB 144        // padded smem row stride bytes (64 halves + 8 pad halves)
#define ROWW 36         // row stride in uint32 words
#define ASTAGE_W (TM * ROWW)            // words per A stage
#define BSTAGE_W (TN * ROWW)            // words per B stage
#define SM_GEMM (NSTAGE * (ASTAGE_W + BSTAGE_W) * 4)   // 110592 bytes

// ======================= scratch (static device globals) ======================
__device__ __half   g_xh[(size_t)NN * D];           // fp16 mirror of x
__device__ float    g_xg[NN * NEXP];                // x @ W_gate (fp32, exact)
__device__ __half   g_aggh[(size_t)NN * D];         // fp16 (GEMM A)
__device__ __half   g_outh[(size_t)NN * TOPK * D];  // expert outputs per slot (fp16)
__device__ __half   g_Wh[NEXP * D * D];             // W transposed [e][n][k], fp16
__device__ int   g_deg[NN];
__device__ int   g_rowstart[NN + 1];
__device__ int   g_cursor[NN];
__device__ int   g_elist[NEDGE];
__device__ int   g_gidx[NN * TOPK];
__device__ float g_gval[NN * TOPK];
__device__ int   g_slot[NN * TOPK];
__device__ float g_imp[NEXP];
__device__ int   g_load[NEXP];
__device__ int   g_pos[NEXP];
__device__ int   g_off[NEXP + 1];
__device__ int   g_toff[NEXP + 1];
__device__ int   g_perm[NN * TOPK];
__device__ int   g_bsum[256];
__device__ int   g_boff[256];
__device__ int   g_is32;

__device__ __forceinline__ uint32_t h2u(__half2 h) {
    return *reinterpret_cast<uint32_t*>(&h);
}
__device__ __forceinline__ void mma16816(float* c, const uint32_t* a, const uint32_t* b) {
    asm volatile("mma.sync.aligned.m16n8k16.row.col.f32.f16.f16.f32 "
        "{%0,%1,%2,%3}, {%4,%5,%6,%7}, {%8,%9}, {%0,%1,%2,%3};"
        : "+f"(c[0]), "+f"(c[1]), "+f"(c[2]), "+f"(c[3])
        : "r"(a[0]), "r"(a[1]), "r"(a[2]), "r"(a[3]), "r"(b[0]), "r"(b[1]));
}
__device__ __forceinline__ uint32_t smem_to_u32(const void* p) {
    uint32_t a;
    asm("{ .reg .u64 t; cvta.to.shared.u64 t, %1; cvt.u32.u64 %0, t; }" : "=r"(a) : "l"(p));
    return a;
}
__device__ __forceinline__ void cpasync16(uint32_t dst, const void* src, bool valid) {
    int sz = valid ? 16 : 0;
    asm volatile("cp.async.ca.shared.global [%0], [%1], 16, %2;"
                 :: "r"(dst), "l"(src), "r"(sz));
}
#define CP_COMMIT() asm volatile("cp.async.commit_group;" ::: "memory")
#define CP_WAIT(n)  asm volatile("cp.async.wait_group %0;" :: "n"(n) : "memory")

// ---------------- init ---------------------------------------------------------
__global__ void init_kernel(const void* __restrict__ ei) {
    int i = blockIdx.x * blockDim.x + threadIdx.x;  // 196*256 = 50176
    if (i < NN) g_deg[i] = 0;
    if (i < NEXP) { g_imp[i] = 0.0f; g_load[i] = 0; g_pos[i] = 0; }
    if (i == 0) {
        const unsigned long long* q = (const unsigned long long*)ei;
        int is32 = 0;
        #pragma unroll
        for (int k = 0; k < 8; k++)
            if (q[k] >= (unsigned long long)NN) is32 = 1;
        g_is32 = is32;
    }
}

__device__ __forceinline__ void load_edge(const void* eiv, int e, int& s, int& dn) {
    if (g_is32) {
        const int* p = (const int*)eiv;
        s = p[e]; dn = p[NEDGE + e];
    } else {
        const long long* p = (const long long*)eiv;
        s = (int)p[e]; dn = (int)p[NEDGE + e];
    }
}

// ---------------- CSR build ----------------------------------------------------
__global__ void hist_kernel(const void* __restrict__ eiv) {
    int e = blockIdx.x * blockDim.x + threadIdx.x;  // exactly NEDGE
    int s, dn; load_edge(eiv, e, s, dn);
    atomicAdd(&g_deg[dn], 1);
}

__global__ void scan1_kernel() {
    __shared__ int ws[8];
    int b = blockIdx.x, t = threadIdx.x;   // grid 196, block 256
    int i = b * 256 + t;
    int v = (i < NN) ? g_deg[i] : 0;
    int x = v;
    int lane = t & 31;
    #pragma unroll
    for (int o = 1; o < 32; o <<= 1) {
        int y = __shfl_up_sync(0xffffffffu, x, o);
        if (lane >= o) x += y;
    }
    if (lane == 31) ws[t >> 5] = x;
    __syncthreads();
    if (t == 0) {
        int s = 0;
        #pragma unroll
        for (int k = 0; k < 8; k++) { int tmp = ws[k]; ws[k] = s; s += tmp; }
        g_bsum[b] = s;
    }
    __syncthreads();
    int incl = x + ws[t >> 5];
    if (i < NN) g_rowstart[i] = incl;
}

__global__ void scan2_kernel() {
    __shared__ int sh[256];
    int t = threadIdx.x;
    sh[t] = (t < 196) ? g_bsum[t] : 0;
    __syncthreads();
    if (t == 0) {
        int s = 0;
        for (int k = 0; k < 196; k++) { int tmp = sh[k]; sh[k] = s; s += tmp; }
    }
    __syncthreads();
    if (t < 196) g_boff[t] = sh[t];
}

__global__ void scan3_kernel() {
    int b = blockIdx.x, t = threadIdx.x;
    int i = b * 256 + t;
    if (i < NN) {
        int st = g_rowstart[i] + g_boff[b] - g_deg[i];
        g_rowstart[i] = st;
        g_cursor[i] = st;
    }
    if (i == 0) g_rowstart[NN] = NEDGE;
}

__global__ void fill_kernel(const void* __restrict__ eiv) {
    int e = blockIdx.x * blockDim.x + threadIdx.x;
    int s, dn; load_edge(eiv, e, s, dn);
    int pos = atomicAdd(&g_cursor[dn], 1);
    g_elist[pos] = s;
}

// ---------------- prep: x -> fp16 mirror + xg = x @ Wg (one warp per row) -----
__global__ void prep_kernel(const float* __restrict__ x, const float* __restrict__ Wg) {
    int w = blockIdx.x * 8 + (threadIdx.x >> 5);   // row, exact 50000
    int lane = threadIdx.x & 31;
    int c0 = lane * 2, c1 = lane * 2 + 1;
    const float4* xr = (const float4*)x + (size_t)w * 64;
    float4 a0 = __ldg(xr + c0), a1 = __ldg(xr + c1);

    // fp16 mirror
    uint2* xh = (uint2*)g_xh + (size_t)w * 64;
    xh[c0] = make_uint2(h2u(__floats2half2_rn(a0.x, a0.y)), h2u(__floats2half2_rn(a0.z, a0.w)));
    xh[c1] = make_uint2(h2u(__floats2half2_rn(a1.x, a1.y)), h2u(__floats2half2_rn(a1.z, a1.w)));

    // xg partial: lane covers Wg rows lane*8 .. lane*8+7
    float p[NEXP] = {0, 0, 0, 0, 0, 0, 0, 0};
    const float* av0 = &a0.x;
    const float* av1 = &a1.x;
    #pragma unroll
    for (int j = 0; j < 4; j++) {
        int row = lane * 8 + j;
        float a = av0[j];
        float4 w0 = __ldg((const float4*)(Wg + (size_t)row * NEXP));
        float4 w1 = __ldg((const float4*)(Wg + (size_t)row * NEXP) + 1);
        p[0] += a * w0.x; p[1] += a * w0.y; p[2] += a * w0.z; p[3] += a * w0.w;
        p[4] += a * w1.x; p[5] += a * w1.y; p[6] += a * w1.z; p[7] += a * w1.w;
    }
    #pragma unroll
    for (int j = 0; j < 4; j++) {
        int row = lane * 8 + 4 + j;
        float a = av1[j];
        float4 w0 = __ldg((const float4*)(Wg + (size_t)row * NEXP));
        float4 w1 = __ldg((const float4*)(Wg + (size_t)row * NEXP) + 1);
        p[0] += a * w0.x; p[1] += a * w0.y; p[2] += a * w0.z; p[3] += a * w0.w;
        p[4] += a * w1.x; p[5] += a * w1.y; p[6] += a * w1.z; p[7] += a * w1.w;
    }
    #pragma unroll
    for (int e = 0; e < NEXP; e++) {
        #pragma unroll
        for (int off = 16; off; off >>= 1)
            p[e] += __shfl_xor_sync(0xffffffffu, p[e], off);
    }
    if (lane == 0) {
        float* xgr = g_xg + w * NEXP;
        #pragma unroll
        for (int e = 0; e < NEXP; e++) xgr[e] = p[e];
    }
}

// ---------------- aggregate (fp16 gather) + gate (exact fp32 via xg) ----------
__global__ void agg_gate_kernel(const float* __restrict__ bg) {
    __shared__ float simp[NEXP];
    __shared__ int   scnt[NEXP];
    int tid = threadIdx.x;
    if (tid < NEXP) { simp[tid] = 0.0f; scnt[tid] = 0; }
    __syncthreads();

    int w = blockIdx.x * 8 + (tid >> 5);   // node, exact 50000
    int lane = tid & 31;
    int start = g_rowstart[w];
    int deg = g_deg[w];
    float a[8] = {0, 0, 0, 0, 0, 0, 0, 0};  // cols lane*8 .. lane*8+7 (fp32 accum)
    float lg = 0.0f;                          // lanes 0-7: logit (lane)
    const uint4* xhb = (const uint4*)g_xh;    // row = 32 uint4
    bool glane = (lane < NEXP);

    int i = 0, end2 = deg & ~1;
    for (; i < end2; i += 2) {
        int s0 = g_elist[start + i], s1 = g_elist[start + i + 1];
        uint4 u0 = __ldg(xhb + (size_t)s0 * 32 + lane);
        uint4 u1 = __ldg(xhb + (size_t)s1 * 32 + lane);
        float g0 = 0.0f, g1 = 0.0f;
        if (glane) {
            g0 = __ldg(g_xg + s0 * NEXP + lane);
            g1 = __ldg(g_xg + s1 * NEXP + lane);
        }
        float2 f0 = __half22float2(*reinterpret_cast<__half2*>(&u0.x));
        float2 f1 = __half22float2(*reinterpret_cast<__half2*>(&u0.y));
        float2 f2 = __half22float2(*reinterpret_cast<__half2*>(&u0.z));
        float2 f3 = __half22float2(*reinterpret_cast<__half2*>(&u0.w));
        a[0] += f0.x; a[1] += f0.y; a[2] += f1.x; a[3] += f1.y;
        a[4] += f2.x; a[5] += f2.y; a[6] += f3.x; a[7] += f3.y;
        f0 = __half22float2(*reinterpret_cast<__half2*>(&u1.x));
        f1 = __half22float2(*reinterpret_cast<__half2*>(&u1.y));
        f2 = __half22float2(*reinterpret_cast<__half2*>(&u1.z));
        f3 = __half22float2(*reinterpret_cast<__half2*>(&u1.w));
        a[0] += f0.x; a[1] += f0.y; a[2] += f1.x; a[3] += f1.y;
        a[4] += f2.x; a[5] += f2.y; a[6] += f3.x; a[7] += f3.y;
        lg += g0 + g1;
    }
    if (i < deg) {
        int s0 = g_elist[start + i];
        uint4 u0 = __ldg(xhb + (size_t)s0 * 32 + lane);
        if (glane) lg += __ldg(g_xg + s0 * NEXP + lane);
        float2 f0 = __half22float2(*reinterpret_cast<__half2*>(&u0.x));
        float2 f1 = __half22float2(*reinterpret_cast<__half2*>(&u0.y));
        float2 f2 = __half22float2(*reinterpret_cast<__half2*>(&u0.z));
        float2 f3 = __half22float2(*reinterpret_cast<__half2*>(&u0.w));
        a[0] += f0.x; a[1] += f0.y; a[2] += f1.x; a[3] += f1.y;
        a[4] += f2.x; a[5] += f2.y; a[6] += f3.x; a[7] += f3.y;
    }

    // write fp16 A row (cols lane*8 .. lane*8+7)
    uint2* ah = (uint2*)g_aggh + (size_t)w * 64;
    ah[lane * 2]     = make_uint2(h2u(__floats2half2_rn(a[0], a[1])), h2u(__floats2half2_rn(a[2], a[3])));
    ah[lane * 2 + 1] = make_uint2(h2u(__floats2half2_rn(a[4], a[5])), h2u(__floats2half2_rn(a[6], a[7])));

    // gate: relu(logit + bias) on lanes 0-7 (exact fp32 path)
    lg = fmaxf(lg + __ldg(bg + (lane & (NEXP - 1))), 0.0f);
    // CONVERGED broadcast: every lane gathers all 8 logits (no shfl in divergence)
    float v[NEXP];
    #pragma unroll
    for (int e = 0; e < NEXP; e++)
        v[e] = __shfl_sync(0xffffffffu, lg, e);
    if (lane == 0) {
        int idx[TOPK]; float val[TOPK];
        #pragma unroll
        for (int k = 0; k < TOPK; k++) {           // strict '>' = lowest index on ties
            int bi = 0; float bv = v[0];
            #pragma unroll
            for (int e = 1; e < NEXP; e++)
                if (v[e] > bv) { bv = v[e]; bi = e; }
            idx[k] = bi; val[k] = bv; v[bi] = -1.0f;
        }
        float mx = val[0];
        float e0 = __expf(val[0] - mx), e1 = __expf(val[1] - mx), e2 = __expf(val[2] - mx);
        float inv = 1.0f / (e0 + e1 + e2);
        float gv[TOPK] = {e0 * inv, e1 * inv, e2 * inv};
        #pragma unroll
        for (int k = 0; k < TOPK; k++) {
            g_gidx[w * TOPK + k] = idx[k];
            g_gval[w * TOPK + k] = gv[k];
            atomicAdd(&simp[idx[k]], gv[k]);
            atomicAdd(&scnt[idx[k]], 1);
        }
    }
    __syncthreads();
    if (tid < NEXP) {
        atomicAdd(&g_imp[tid], simp[tid]);
        atomicAdd(&g_load[tid], scnt[tid]);
    }
}

// ---------------- per-expert offsets ------------------------------------------
__global__ void offsets_kernel() {
    if (threadIdx.x == 0 && blockIdx.x == 0) {
        int o = 0, t = 0;
        for (int e = 0; e < NEXP; e++) {
            g_off[e] = o; g_toff[e] = t;
            o += g_load[e];
            t += (g_load[e] + TM - 1) / TM;
        }
        g_off[NEXP] = o; g_toff[NEXP] = t;
    }
}

// ---------------- build per-expert node lists ---------------------------------
__global__ void build_lists_kernel() {
    __shared__ int lc[NEXP];
    __shared__ int lb[NEXP];
    int tid = threadIdx.x;
    if (tid < NEXP) lc[tid] = 0;
    __syncthreads();
    int p = blockIdx.x * blockDim.x + tid;
    bool valid = (p < NN * TOPK);
    int e = 0, rank = 0, n = 0;
    if (valid) {
        n = p / TOPK;
        e = g_gidx[p];
        rank = atomicAdd(&lc[e], 1);
    }
    __syncthreads();
    if (tid < NEXP) lb[tid] = atomicAdd(&g_pos[tid], lc[tid]);
    __syncthreads();
    if (valid) {
        int slot = g_off[e] + lb[e] + rank;
        g_perm[slot] = n;
        g_slot[p] = slot;
    }
}

// ---------------- transpose W -> fp16: [e][k][n] -> [e][n][k] -----------------
__global__ void transW_kernel(const float* __restrict__ W) {
    __shared__ float tl[32][33];
    int e = blockIdx.z, kb = blockIdx.y * 32, nb = blockIdx.x * 32;
    int tx = threadIdx.x, ty = threadIdx.y;  // (32, 8)
    const float* Wb = W + (size_t)e * D * D;
    __half* Tb = g_Wh + (size_t)e * D * D;
    #pragma unroll
    for (int j = 0; j < 4; j++)
        tl[ty + 8 * j][tx] = Wb[(size_t)(kb + ty + 8 * j) * D + nb + tx];
    __syncthreads();
    #pragma unroll
    for (int j = 0; j < 4; j++)
        Tb[(size_t)(nb + ty + 8 * j) * D + kb + tx] = __float2half_rn(tl[tx][ty + 8 * j]);
}

// ---------------- fp16 m16n8k16 grouped GEMM: 128x256, 512 threads ------------
// KC=64 halves per chunk (4 chunks), NSTAGE=2 double buffer: half the barriers
// of the KC=32 version, same total smem traffic, identical accumulation order.
__global__ void __launch_bounds__(512, 1)
moe_gemm_mma() {
    extern __shared__ uint32_t smem[];
    uint32_t* sA = smem;                         // [NSTAGE][TM*ROWW]
    uint32_t* sB = smem + NSTAGE * ASTAGE_W;     // [NSTAGE][TN*ROWW]

    int tile = blockIdx.x;
    if (tile >= g_toff[NEXP]) return;
    int e = 0;
    while (e < NEXP - 1 && tile >= g_toff[e + 1]) e++;
    int mt0 = tile - g_toff[e];
    int base = g_off[e] + mt0 * TM;
    int rows = g_load[e] - mt0 * TM;
    if (rows > TM) rows = TM;

    int tid = threadIdx.x;
    int wid = tid >> 5, lane = tid & 31;
    int gid = lane >> 2, tid4 = lane & 3;
    int wm = wid & 1, wn = wid >> 1;             // warp tile (wm*64, wn*32)

    // A staging: 4 threads per row (ra = tid>>2, qa = tid&3), 2 x 16B each
    int ra = tid >> 2, qa = tid & 3;
    const uint4* Af = nullptr;
    if (ra < rows) Af = (const uint4*)(g_aggh + (size_t)g_perm[base + ra] * D);
    // B staging: 2 threads per row (rb = tid>>1, hb = tid&1), 4 x 16B each
    int rb = tid >> 1, hb = tid & 1;
    const uint4* Bf = (const uint4*)(g_Wh + ((size_t)e * D + rb) * D);

    uint32_t sbase = smem_to_u32(smem);
    uint32_t aAddr = sbase + (uint32_t)(ra * ROWB + qa * 32);
    uint32_t bAddr = sbase + (uint32_t)(NSTAGE * ASTAGE_W * 4 + rb * ROWB + hb * 64);

    float acc[4][4][4];
    #pragma unroll
    for (int i = 0; i < 4; i++)
        #pragma unroll
        for (int j = 0; j < 4; j++)
            #pragma unroll
            for (int q = 0; q < 4; q++) acc[i][j][q] = 0.0f;

    // prologue: stage chunk 0 into buffer 0
    {
        #pragma unroll
        for (int j = 0; j < 2; j++)
            cpasync16(aAddr + j * 16, Af ? (const void*)(Af + qa * 2 + j)
                                         : (const void*)g_aggh, Af != nullptr);
        #pragma unroll
        for (int j = 0; j < 4; j++)
            cpasync16(bAddr + j * 16, (const void*)(Bf + hb * 4 + j), true);
        CP_COMMIT();
    }

    #pragma unroll
    for (int c = 0; c < D * 2 / KC / 2; c++) {   // 4 chunks (K=256 -> 128 half-pairs... c<4)
        if (c + 1 < 4) {
            int buf = (c + 1) & 1;
            uint32_t ao = aAddr + (uint32_t)(buf * ASTAGE_W * 4);
            uint32_t bo = bAddr + (uint32_t)(buf * BSTAGE_W * 4);
            #pragma unroll
            for (int j = 0; j < 2; j++)
                cpasync16(ao + j * 16, Af ? (const void*)(Af + (c + 1) * 8 + qa * 2 + j)
                                          : (const void*)g_aggh, Af != nullptr);
            #pragma unroll
            for (int j = 0; j < 4; j++)
                cpasync16(bo + j * 16, (const void*)(Bf + (c + 1) * 8 + hb * 4 + j), true);
        }
        CP_COMMIT();                 // uniform group depth
        CP_WAIT(1);
        __syncthreads();

        const uint32_t* A = sA + (c & 1) * ASTAGE_W;
        const uint32_t* B = sB + (c & 1) * BSTAGE_W;
        #pragma unroll
        for (int ks = 0; ks < 4; ks++) {     // four k16 steps per 64-half chunk
            int kk = ks * 8 + tid4;          // half-pair index within chunk
            uint32_t af[4][4], bf[4][2];
            #pragma unroll
            for (int mi = 0; mi < 4; mi++) {
                int rowa = wm * 64 + mi * 16 + gid;
                af[mi][0] = A[rowa * ROWW + kk];
                af[mi][1] = A[(rowa + 8) * ROWW + kk];
                af[mi][2] = A[rowa * ROWW + kk + 4];
                af[mi][3] = A[(rowa + 8) * ROWW + kk + 4];
            }
            #pragma unroll
            for (int ni = 0; ni < 4; ni++) {
                int coln = wn * 32 + ni * 8 + gid;
                bf[ni][0] = B[coln * ROWW + kk];
                bf[ni][1] = B[coln * ROWW + kk + 4];
            }
            #pragma unroll
            for (int mi = 0; mi < 4; mi++)
                #pragma unroll
                for (int ni = 0; ni < 4; ni++)
                    mma16816(acc[mi][ni], af[mi], bf[ni]);
        }
        __syncthreads();
    }

    // epilogue: fp16 stores to g_outh (no atomics)
    #pragma unroll
    for (int mi = 0; mi < 4; mi++) {
        int mm0 = wm * 64 + mi * 16 + gid;
        int mm1 = mm0 + 8;
        __half* r0 = g_outh + (size_t)(base + mm0) * D;
        __half* r1 = g_outh + (size_t)(base + mm1) * D;
        #pragma unroll
        for (int ni = 0; ni < 4; ni++) {
            int col = wn * 32 + ni * 8 + tid4 * 2;
            if (mm0 < rows) *(uint32_t*)(r0 + col) = h2u(__floats2half2_rn(acc[mi][ni][0], acc[mi][ni][1]));
            if (mm1 < rows) *(uint32_t*)(r1 + col) = h2u(__floats2half2_rn(acc[mi][ni][2], acc[mi][ni][3]));
        }
    }
}

// ---------------- combine + loss ----------------------------------------------
__global__ void combine_kernel(const float* __restrict__ bexp, float* __restrict__ y,
                               int out_size) {
    int idx = blockIdx.x * blockDim.x + threadIdx.x;  // NN*64 exact
    int n = idx >> 6, c4 = idx & 63;
    float4 acc = make_float4(0, 0, 0, 0);
    #pragma unroll
    for (int k = 0; k < TOPK; k++) {
        int p = n * TOPK + k;
        int slot = g_slot[p];
        float gv = g_gval[p];
        int ex = g_gidx[p];
        uint2 ou = __ldg((const uint2*)(g_outh + (size_t)slot * D) + c4);
        float2 o01 = __half22float2(*reinterpret_cast<__half2*>(&ou.x));
        float2 o23 = __half22float2(*reinterpret_cast<__half2*>(&ou.y));
        float4 b = __ldg((const float4*)(bexp + (size_t)ex * D) + c4);
        acc.x += gv * (o01.x + b.x);
        acc.y += gv * (o01.y + b.y);
        acc.z += gv * (o23.x + b.z);
        acc.w += gv * (o23.y + b.w);
    }
    *((float4*)y + (size_t)n * 64 + c4) = acc;

    if (idx == 0) {
        float mi = 0.0f, ml = 0.0f;
        for (int e = 0; e < NEXP; e++) { mi += g_imp[e]; ml += (float)g_load[e]; }
        mi *= (1.0f / NEXP); ml *= (1.0f / NEXP);
        float vi = 0.0f, vl = 0.0f;
        for (int e = 0; e < NEXP; e++) {
            float di = g_imp[e] - mi;         vi += di * di;
            float dl = (float)g_load[e] - ml; vl += dl * dl;
        }
        vi *= (1.0f / (NEXP - 1));
        vl *= (1.0f / (NEXP - 1));
        float loss = 0.01f * (vi / (mi * mi + 1e-10f) + vl / (ml * ml + 1e-10f));
        if (out_size > NN * D) y[NN * D] = loss;
    }
}

// ---------------- launch ------------------------------------------------------
extern "C" void kernel_launch(void* const* d_in, const int* in_sizes, int n_in,
                              void* d_out, int out_size) {
    const float* x    = (const float*)d_in[0];
    const void*  ei   = d_in[1];
    const float* Wg   = (const float*)d_in[2];
    const float* bg   = (const float*)d_in[3];
    const float* Wexp = (const float*)d_in[4];
    const float* bexp = (const float*)d_in[5];
    float* y = (float*)d_out;

    cudaFuncSetAttribute(moe_gemm_mma, cudaFuncAttributeMaxDynamicSharedMemorySize, SM_GEMM);

    init_kernel<<<196, 256>>>(ei);
    hist_kernel<<<NEDGE / 256, 256>>>(ei);
    scan1_kernel<<<196, 256>>>();
    scan2_kernel<<<1, 256>>>();
    scan3_kernel<<<196, 256>>>();
    fill_kernel<<<NEDGE / 256, 256>>>(ei);
    prep_kernel<<<NN / 8, 256>>>(x, Wg);
    transW_kernel<<<dim3(8, 8, NEXP), dim3(32, 8)>>>(Wexp);
    agg_gate_kernel<<<NN / 8, 256>>>(bg);
    offsets_kernel<<<1, 32>>>();
    build_lists_kernel<<<(NN * TOPK + 255) / 256, 256>>>();
    int max_tiles = (NN * TOPK) / TM + NEXP;  // upper bound on total tiles
    moe_gemm_mma<<<max_tiles, 512, SM_GEMM>>>();
    combine_kernel<<<NN * 64 / 256, 256>>>(bexp, y, out_size);
}